// round 6
// baseline (speedup 1.0000x reference)
#include <cuda_runtime.h>

#define NG 8192
#define NC 4096
#define FGk 512
#define FCk 256
#define ALPHA 0.2f

typedef unsigned long long ull;

// ---------------- scratch (static device allocations) ----------------
__device__ float g_gene_h[NG * 64];
__device__ float g_cell_h[NC * 64];
// per-node exp pairs {exp(s), exp(ALPHA*s)} for each relation side
__device__ float2 g_e_gg1[NG], g_e_gg2[NG], g_e_gc1[NG], g_e_cg2[NG];
__device__ float2 g_e_cc1[NC], g_e_cc2[NC], g_e_gc2[NC], g_e_cg1[NC];
__device__ float g_gam_g[NG], g_gam_c[NC];
// unnormalized numerators / denominators (gg, cg split into 2 j-halves)
__device__ float g_Ngg0[NG * 64], g_Ngg1[NG * 64];
__device__ float g_lgg0[NG], g_lgg1[NG];
__device__ float g_Ngc[NG * 64], g_lgc[NG];
__device__ float g_Ncc[NC * 64], g_lcc[NC];
__device__ float g_Ncg0[NC * 64], g_Ncg1[NC * 64];
__device__ float g_lcg0[NC], g_lcg1[NC];

__device__ __forceinline__ float leaky(float x) { return x >= 0.f ? x : ALPHA * x; }

// packed fp32x2 FMA: d = a*b + d (lanewise)
#define FFMA2(d, a, b) asm("fma.rn.f32x2 %0, %1, %2, %0;" : "+l"(d) : "l"(a), "l"(b))

__device__ __forceinline__ ull pack2(float a, float b) {
    ull r;
    asm("mov.b64 %0, {%1, %2};" : "=l"(r) : "f"(a), "f"(b));
    return r;
}

// ---------------- feature GEMM: H[M,64] = X[M,K] @ W[K,64] ----------------
__global__ void gemm64_kernel(const float* __restrict__ X, const float* __restrict__ W,
                              int K, int which) {
    __shared__ float xs[16 * FGk];
    float* H = which ? g_cell_h : g_gene_h;
    const int m0 = blockIdx.x * 16;
    const int tid = threadIdx.x;

    const int nf4 = 16 * K / 4;
    const float4* src = (const float4*)(X + (size_t)m0 * K);
    float4* dst = (float4*)xs;
    for (int i = tid; i < nf4; i += 256) dst[i] = src[i];
    __syncthreads();

    const int d = tid & 63;
    const int rg = tid >> 6;
    float a0 = 0.f, a1 = 0.f, a2 = 0.f, a3 = 0.f;
    const float* xr = xs + (rg * 4) * K;
#pragma unroll 4
    for (int k = 0; k < K; k++) {
        float w = W[k * 64 + d];
        a0 += xr[k] * w;
        a1 += xr[K + k] * w;
        a2 += xr[2 * K + k] * w;
        a3 += xr[3 * K + k] * w;
    }
    const int row = m0 + rg * 4;
    H[(row + 0) * 64 + d] = a0;
    H[(row + 1) * 64 + d] = a1;
    H[(row + 2) * 64 + d] = a2;
    H[(row + 3) * 64 + d] = a3;
}

// ---------------- score vectors -> exp pairs + gates ----------------
__device__ __forceinline__ float warp_dot(float v0, float v1, const float* __restrict__ vec, int lane) {
    float t = v0 * vec[lane] + v1 * vec[lane + 32];
#pragma unroll
    for (int off = 16; off; off >>= 1) t += __shfl_xor_sync(0xFFFFFFFFu, t, off);
    return t;
}

__global__ void svec_kernel(const float* __restrict__ a_gg, const float* __restrict__ a_gc,
                            const float* __restrict__ a_cc, const float* __restrict__ a_cg,
                            const float* __restrict__ Wg, const float* __restrict__ bg,
                            const float* __restrict__ Wc, const float* __restrict__ bc) {
    const int w = blockIdx.x * 8 + (threadIdx.x >> 5);
    const int lane = threadIdx.x & 31;
    if (w < NG) {
        const float* h = g_gene_h + (size_t)w * 64;
        float v0 = h[lane], v1 = h[lane + 32];
        float d1 = warp_dot(v0, v1, a_gg, lane);       // gg src
        float d2 = warp_dot(v0, v1, a_gg + 64, lane);  // gg dst
        float d3 = warp_dot(v0, v1, a_gc, lane);       // gc src
        float d4 = warp_dot(v0, v1, a_cg + 64, lane);  // cg dst
        float dg = warp_dot(v0, v1, Wg, lane);
        if (lane == 0) {
            g_e_gg1[w] = make_float2(expf(d1), expf(ALPHA * d1));
            g_e_gg2[w] = make_float2(expf(d2), expf(ALPHA * d2));
            g_e_gc1[w] = make_float2(expf(d3), expf(ALPHA * d3));
            g_e_cg2[w] = make_float2(expf(d4), expf(ALPHA * d4));
            g_gam_g[w] = 1.0f / (1.0f + expf(-(dg + bg[0])));
        }
    } else if (w < NG + NC) {
        const int r = w - NG;
        const float* h = g_cell_h + (size_t)r * 64;
        float v0 = h[lane], v1 = h[lane + 32];
        float d1 = warp_dot(v0, v1, a_cc, lane);       // cc src
        float d2 = warp_dot(v0, v1, a_cc + 64, lane);  // cc dst
        float d3 = warp_dot(v0, v1, a_gc + 64, lane);  // gc dst
        float d4 = warp_dot(v0, v1, a_cg, lane);       // cg src
        float dg = warp_dot(v0, v1, Wc, lane);
        if (lane == 0) {
            g_e_cc1[r] = make_float2(expf(d1), expf(ALPHA * d1));
            g_e_cc2[r] = make_float2(expf(d2), expf(ALPHA * d2));
            g_e_gc2[r] = make_float2(expf(d3), expf(ALPHA * d3));
            g_e_cg1[r] = make_float2(expf(d4), expf(ALPHA * d4));
            g_gam_c[r] = 1.0f / (1.0f + expf(-(dg + bc[0])));
        }
    }
}

// ---------------- fused relation kernel ----------------
// 576 uniform blocks, each: 64 src rows x 4096 dst cols (64 j-tiles of 64).
// [0,256)   gg: i-tile = b>>1, j-half = b&1
// [256,384) gc
// [384,448) cc
// [448,576) cg (transposed adj): i-tile = (b-448)>>1, j-half = (b-448)&1
__global__ __launch_bounds__(256) void rel_kernel(const int* __restrict__ gadj,
                                                  const int* __restrict__ cadj,
                                                  const int* __restrict__ gca) {
    __shared__ float4 hdupA[64 * 16];   // {h[4t],h[4t],h[4t+1],h[4t+1]} per (jj,t)
    __shared__ float4 hdupB[64 * 16];   // {h[4t+2],h[4t+2],h[4t+3],h[4t+3]}
    __shared__ float2 s2sh[64];
    __shared__ unsigned char adjsh[64 * 64];

    const int b = blockIdx.x;
    const float2 *e1, *e2;
    const float* hd;
    const int* adj;
    float *Nout, *lout;
    int i0, j0base, rs;
    bool trans = false;
    if (b < 256) {
        i0 = (b >> 1) * 64; j0base = (b & 1) * 4096;
        e1 = g_e_gg1; e2 = g_e_gg2; hd = g_gene_h; adj = gadj; rs = NG;
        Nout = (b & 1) ? g_Ngg1 : g_Ngg0; lout = (b & 1) ? g_lgg1 : g_lgg0;
    } else if (b < 384) {
        i0 = (b - 256) * 64; j0base = 0;
        e1 = g_e_gc1; e2 = g_e_gc2; hd = g_cell_h; adj = gca; rs = NC;
        Nout = g_Ngc; lout = g_lgc;
    } else if (b < 448) {
        i0 = (b - 384) * 64; j0base = 0;
        e1 = g_e_cc1; e2 = g_e_cc2; hd = g_cell_h; adj = cadj; rs = NC;
        Nout = g_Ncc; lout = g_lcc;
    } else {
        const int bb = b - 448;
        i0 = (bb >> 1) * 64; j0base = (bb & 1) * 4096;
        e1 = g_e_cg1; e2 = g_e_cg2; hd = g_gene_h; adj = gca; rs = NC; trans = true;
        Nout = (bb & 1) ? g_Ncg1 : g_Ncg0; lout = (bb & 1) ? g_lcg1 : g_lcg0;
    }

    const int tid = threadIdx.x;
    const int tx = tid & 15;      // d-group (and col-group in score phase)
    const int ty = tid >> 4;      // row-group
    const int r0 = ty * 4, d0 = tx * 4;

    // hoist src-side exp pairs for my 4 rows
    float E1p[4], E1n[4];
#pragma unroll
    for (int rr = 0; rr < 4; rr++) {
        float2 v = e1[i0 + r0 + rr];
        E1p[rr] = v.x; E1n[rr] = v.y;
    }

    ull acc[2][4];
#pragma unroll
    for (int rp = 0; rp < 2; rp++)
#pragma unroll
        for (int dd = 0; dd < 4; dd++) acc[rp][dd] = 0ull;
    float lp[4] = {0.f, 0.f, 0.f, 0.f};

    for (int jt = 0; jt < 64; jt++) {
        const int j0 = j0base + jt * 64;
        if (tid < 64) s2sh[tid] = e2[j0 + tid];

        // h tile -> duplicated smem
#pragma unroll
        for (int ph = 0; ph < 4; ph++) {
            int idx = tid + ph * 256;           // 0..1023 float4 slots
            int jj = idx >> 4, dq = idx & 15;
            float4 f = *(const float4*)&hd[(size_t)(j0 + jj) * 64 + dq * 4];
            hdupA[jj * 16 + dq] = make_float4(f.x, f.x, f.y, f.y);
            hdupB[jj * 16 + dq] = make_float4(f.z, f.z, f.w, f.w);
        }
        // adjacency tile -> bytes
        if (!trans) {
#pragma unroll
            for (int q = 0; q < 4; q++) {
                int i4 = tid + q * 256;
                int r = i4 >> 4, c0 = (i4 & 15) << 2;
                int4 v = *(const int4*)&adj[(size_t)(i0 + r) * rs + j0 + c0];
                *(uchar4*)&adjsh[r * 64 + c0] =
                    make_uchar4(v.x > 0, v.y > 0, v.z > 0, v.w > 0);
            }
        } else {
#pragma unroll
            for (int q = 0; q < 4; q++) {
                int i4 = tid + q * 256;
                int c = i4 >> 4, rB = (i4 & 15) << 2;
                int4 v = *(const int4*)&adj[(size_t)(j0 + c) * rs + i0 + rB];
                adjsh[(rB + 0) * 64 + c] = (unsigned char)(v.x > 0);
                adjsh[(rB + 1) * 64 + c] = (unsigned char)(v.y > 0);
                adjsh[(rB + 2) * 64 + c] = (unsigned char)(v.z > 0);
                adjsh[(rB + 3) * 64 + c] = (unsigned char)(v.w > 0);
            }
        }
        __syncthreads();

        // ---- score: p = adj ? (q>=1 ? E1p*E2p : E1n*E2n) : 0  (no exp, no max) ----
        const unsigned au0 = *(const unsigned*)&adjsh[(r0 + 0) * 64 + d0];
        const unsigned au1 = *(const unsigned*)&adjsh[(r0 + 1) * 64 + d0];
        const unsigned au2 = *(const unsigned*)&adjsh[(r0 + 2) * 64 + d0];
        const unsigned au3 = *(const unsigned*)&adjsh[(r0 + 3) * 64 + d0];
        ull P01[4], P23[4];
#pragma unroll
        for (int cc = 0; cc < 4; cc++) {
            const float2 E2 = s2sh[d0 + cc];
            float q0 = E1p[0] * E2.x, p0 = (q0 >= 1.f) ? q0 : E1n[0] * E2.y;
            float q1 = E1p[1] * E2.x, p1 = (q1 >= 1.f) ? q1 : E1n[1] * E2.y;
            float q2 = E1p[2] * E2.x, p2 = (q2 >= 1.f) ? q2 : E1n[2] * E2.y;
            float q3 = E1p[3] * E2.x, p3 = (q3 >= 1.f) ? q3 : E1n[3] * E2.y;
            p0 = ((au0 >> (cc * 8)) & 255u) ? p0 : 0.f;
            p1 = ((au1 >> (cc * 8)) & 255u) ? p1 : 0.f;
            p2 = ((au2 >> (cc * 8)) & 255u) ? p2 : 0.f;
            p3 = ((au3 >> (cc * 8)) & 255u) ? p3 : 0.f;
            lp[0] += p0; lp[1] += p1; lp[2] += p2; lp[3] += p3;
            P01[cc] = pack2(p0, p1);
            P23[cc] = pack2(p2, p3);
        }

        // ---- P @ H via FFMA2; p pairs broadcast by 64-bit shuffle within 16-lane half ----
#pragma unroll 4
        for (int jj = 0; jj < 64; jj++) {
            const ull p01 = __shfl_sync(0xFFFFFFFFu, P01[jj & 3], jj >> 2, 16);
            const ull p23 = __shfl_sync(0xFFFFFFFFu, P23[jj & 3], jj >> 2, 16);
            const ulonglong2 hA = *(const ulonglong2*)&hdupA[jj * 16 + tx];
            const ulonglong2 hB = *(const ulonglong2*)&hdupB[jj * 16 + tx];
            FFMA2(acc[0][0], p01, hA.x);
            FFMA2(acc[0][1], p01, hA.y);
            FFMA2(acc[0][2], p01, hB.x);
            FFMA2(acc[0][3], p01, hB.y);
            FFMA2(acc[1][0], p23, hA.x);
            FFMA2(acc[1][1], p23, hA.y);
            FFMA2(acc[1][2], p23, hB.x);
            FFMA2(acc[1][3], p23, hB.y);
        }
        __syncthreads();
    }

    // ---- epilogue: reduce l over the 16 col-lanes, store unnormalized N ----
#pragma unroll
    for (int rr = 0; rr < 4; rr++) {
        float v = lp[rr];
        v += __shfl_xor_sync(0xFFFFFFFFu, v, 1, 16);
        v += __shfl_xor_sync(0xFFFFFFFFu, v, 2, 16);
        v += __shfl_xor_sync(0xFFFFFFFFu, v, 4, 16);
        v += __shfl_xor_sync(0xFFFFFFFFu, v, 8, 16);
        lp[rr] = v;
    }
    if (tx == 0) {
#pragma unroll
        for (int rr = 0; rr < 4; rr++) lout[i0 + r0 + rr] = lp[rr];
    }
#pragma unroll
    for (int rp = 0; rp < 2; rp++) {
        float lo[4], hi[4];
#pragma unroll
        for (int dd = 0; dd < 4; dd++) {
            lo[dd] = __uint_as_float((unsigned)(acc[rp][dd] & 0xFFFFFFFFull));
            hi[dd] = __uint_as_float((unsigned)(acc[rp][dd] >> 32));
        }
        const int row = i0 + r0 + rp * 2;
        *(float4*)&Nout[(size_t)row * 64 + d0] = make_float4(lo[0], lo[1], lo[2], lo[3]);
        *(float4*)&Nout[(size_t)(row + 1) * 64 + d0] = make_float4(hi[0], hi[1], hi[2], hi[3]);
    }
}

// ---------------- final combine (merge halves, normalize, gate, residual, leaky) ----------------
__global__ void combine_kernel(float* __restrict__ out) {
    const int idx4 = blockIdx.x * blockDim.x + threadIdx.x;
    const int e = idx4 * 4;
    if (e < NG * 64) {
        const int i = e >> 6;
        const float lg = g_lgg0[i] + g_lgg1[i];
        const float invgg = lg > 0.f ? 1.0f / lg : 0.f;
        const float lc = g_lgc[i];
        const float invgc = lc > 0.f ? 1.0f / lc : 0.f;
        const float ga = g_gam_g[i];
        float4 h = *(float4*)&g_gene_h[e];
        float4 A0 = *(float4*)&g_Ngg0[e];
        float4 A1 = *(float4*)&g_Ngg1[e];
        float4 B = *(float4*)&g_Ngc[e];
        float4 o;
        o.x = leaky(h.x + (A0.x + A1.x) * invgg + ga * B.x * invgc);
        o.y = leaky(h.y + (A0.y + A1.y) * invgg + ga * B.y * invgc);
        o.z = leaky(h.z + (A0.z + A1.z) * invgg + ga * B.z * invgc);
        o.w = leaky(h.w + (A0.w + A1.w) * invgg + ga * B.w * invgc);
        *(float4*)&out[e] = o;
    } else if (e < (NG + NC) * 64) {
        const int e2 = e - NG * 64;
        const int i = e2 >> 6;
        const float lcc_ = g_lcc[i];
        const float invcc = lcc_ > 0.f ? 1.0f / lcc_ : 0.f;
        const float lcg_ = g_lcg0[i] + g_lcg1[i];
        const float invcg = lcg_ > 0.f ? 1.0f / lcg_ : 0.f;
        const float gc_ = g_gam_c[i];
        float4 h = *(float4*)&g_cell_h[e2];
        float4 A = *(float4*)&g_Ncc[e2];
        float4 B0 = *(float4*)&g_Ncg0[e2];
        float4 B1 = *(float4*)&g_Ncg1[e2];
        float4 o;
        o.x = leaky(h.x + A.x * invcc + gc_ * (B0.x + B1.x) * invcg);
        o.y = leaky(h.y + A.y * invcc + gc_ * (B0.y + B1.y) * invcg);
        o.z = leaky(h.z + A.z * invcc + gc_ * (B0.z + B1.z) * invcg);
        o.w = leaky(h.w + A.w * invcc + gc_ * (B0.w + B1.w) * invcg);
        *(float4*)&out[e] = o;
    }
}

// ---------------- launch ----------------
extern "C" void kernel_launch(void* const* d_in, const int* in_sizes, int n_in,
                              void* d_out, int out_size) {
    const float* gene_x  = (const float*)d_in[0];
    const float* cell_x  = (const float*)d_in[1];
    const float* W_g     = (const float*)d_in[2];
    const float* W_c     = (const float*)d_in[3];
    const float* a_gg    = (const float*)d_in[4];
    const float* a_gc    = (const float*)d_in[5];
    const float* a_cc    = (const float*)d_in[6];
    const float* a_cg    = (const float*)d_in[7];
    const float* Wgate_g = (const float*)d_in[8];
    const float* bgate_g = (const float*)d_in[9];
    const float* Wgate_c = (const float*)d_in[10];
    const float* bgate_c = (const float*)d_in[11];
    const int* gene_adj  = (const int*)d_in[12];
    const int* cell_adj  = (const int*)d_in[13];
    const int* gca       = (const int*)d_in[14];
    float* out = (float*)d_out;

    gemm64_kernel<<<NG / 16, 256>>>(gene_x, W_g, FGk, 0);
    gemm64_kernel<<<NC / 16, 256>>>(cell_x, W_c, FCk, 1);
    svec_kernel<<<(NG + NC) / 8, 256>>>(a_gg, a_gc, a_cc, a_cg,
                                        Wgate_g, bgate_g, Wgate_c, bgate_c);
    rel_kernel<<<576, 256>>>(gene_adj, cell_adj, gca);
    combine_kernel<<<((NG + NC) * 64 / 4) / 256, 256>>>(out);
}